// round 1
// baseline (speedup 1.0000x reference)
#include <cuda_runtime.h>
#include <cuda_bf16.h>
#include <math.h>
#include <stdint.h>

// Problem constants
#define E_   16
#define H_   2048
#define I_   768
#define T_   4096
#define TWOI 1536
#define K2DIM (E_ * I_)   // 12288

// Tiling
#define BM 128
#define BN 128
#define BK 16
#define AS_LD 20     // 16 + 4 pad  -> bank (20r+c)%32 conflict-free for frag reads
#define BS_LD 132    // 128 + 4 pad -> bank (4k+n)%32 conflict-free for frag reads

#define AS_SZ (2 * BM * AS_LD)           // floats, double buffered
#define BT_SZ (2 * BK * BS_LD)           // floats, double buffered (one B tile)
#define SMEM1_FLOATS (AS_SZ + 2 * BT_SZ) // A + Bgate + Bup
#define SMEM1_BYTES  (SMEM1_FLOATS * 4)  // 54,272 B
#define SMEM2_FLOATS (AS_SZ + BT_SZ)
#define SMEM2_BYTES  (SMEM2_FLOATS * 4)  // 37,376 B

// 201 MB scratch for inter = rw * up * silu(gate), laid out [T, E*I]
__device__ float g_inter[(size_t)T_ * K2DIM];

__device__ __forceinline__ unsigned f2tf(float x) {
    unsigned u;
    asm("cvt.rna.tf32.f32 %0, %1;" : "=r"(u) : "f"(x));
    return u;
}

__device__ __forceinline__ void mma_tf32(float c[4],
                                         unsigned a0, unsigned a1, unsigned a2, unsigned a3,
                                         unsigned b0, unsigned b1) {
    asm volatile(
        "mma.sync.aligned.m16n8k8.row.col.f32.tf32.tf32.f32 "
        "{%0,%1,%2,%3}, {%4,%5,%6,%7}, {%8,%9}, {%0,%1,%2,%3};\n"
        : "+f"(c[0]), "+f"(c[1]), "+f"(c[2]), "+f"(c[3])
        : "r"(a0), "r"(a1), "r"(a2), "r"(a3), "r"(b0), "r"(b1));
}

// ---------------------------------------------------------------------------
// Kernel 1: inter[t, e*768+j] = rw[t,e] * up * silu(gate)
//   gate = sum_h X[t,h] * GU[e,h,j]      * gsc[e,h/128, j/128]
//   up   = sum_h X[t,h] * GU[e,h,768+j]  * gsc[e,h/128, 6 + j/128]
// Block: 128 rows (t) x 128 cols (j local within expert). 768 % 128 == 0, so
// each block sits inside one expert and one scale column.
// ---------------------------------------------------------------------------
__global__ void __launch_bounds__(256, 1)
k1_gateup_silu(const float* __restrict__ X,    // [T, H]
               const float* __restrict__ RW,   // [T, E]
               const float* __restrict__ GU,   // [E, H, 2I]
               const float* __restrict__ GUS)  // [E, 16, 12]
{
    extern __shared__ float sm[];
    float* As = sm;                 // [2][BM][AS_LD]
    float* Bg = sm + AS_SZ;         // [2][BK][BS_LD]
    float* Bu = Bg + BT_SZ;         // [2][BK][BS_LD]

    const int tid    = threadIdx.x;
    const int wid    = tid >> 5;
    const int lane   = tid & 31;
    const int g      = lane >> 2;   // 0..7
    const int tg     = lane & 3;    // 0..3
    const int warp_m = wid & 1;     // 0..1 -> 64 rows each
    const int warp_n = wid >> 1;    // 0..3 -> 32 cols each

    const int m0 = blockIdx.y * BM;
    const int n0 = blockIdx.x * BN;     // global inter column
    const int e  = n0 / I_;
    const int j0 = n0 % I_;             // multiple of 128

    const float* guE = GU + (size_t)e * H_ * TWOI;
    const float* gsE = GUS + e * 16 * 12;

    float cg[4][4][4], cu[4][4][4];
#pragma unroll
    for (int a = 0; a < 4; a++)
#pragma unroll
        for (int b = 0; b < 4; b++)
#pragma unroll
            for (int c = 0; c < 4; c++) { cg[a][b][c] = 0.f; cu[a][b][c] = 0.f; }

    // gmem -> reg staging layout
    const int a_row = tid >> 2;            // 0..63 (two iters: +0, +64)
    const int a_c4  = (tid & 3) * 4;       // 0,4,8,12
    const int b_row = tid >> 5;            // 0..7 (two iters: +0, +8)
    const int b_c4  = (tid & 31) * 4;      // 0..124

    float4 aR[2], bgR[2], buR[2];
    float sG, sU;

    auto LOAD = [&](int k0) {
#pragma unroll
        for (int i = 0; i < 2; i++)
            aR[i] = *reinterpret_cast<const float4*>(
                X + (size_t)(m0 + a_row + i * 64) * H_ + k0 + a_c4);
        sG = gsE[(k0 >> 7) * 12 + (j0 >> 7)];
        sU = gsE[(k0 >> 7) * 12 + 6 + (j0 >> 7)];
#pragma unroll
        for (int i = 0; i < 2; i++) {
            size_t roff = (size_t)(k0 + b_row + i * 8) * TWOI;
            bgR[i] = *reinterpret_cast<const float4*>(guE + roff + j0 + b_c4);
            buR[i] = *reinterpret_cast<const float4*>(guE + roff + I_ + j0 + b_c4);
        }
    };

    auto STORE = [&](int st) {
        float* Ad = As + st * BM * AS_LD;
#pragma unroll
        for (int i = 0; i < 2; i++) {
            float* p = Ad + (a_row + i * 64) * AS_LD + a_c4;
            p[0] = __uint_as_float(f2tf(aR[i].x));
            p[1] = __uint_as_float(f2tf(aR[i].y));
            p[2] = __uint_as_float(f2tf(aR[i].z));
            p[3] = __uint_as_float(f2tf(aR[i].w));
        }
        float* Bgd = Bg + st * BK * BS_LD;
        float* Bud = Bu + st * BK * BS_LD;
#pragma unroll
        for (int i = 0; i < 2; i++) {
            float* pg = Bgd + (b_row + i * 8) * BS_LD + b_c4;
            pg[0] = __uint_as_float(f2tf(bgR[i].x * sG));
            pg[1] = __uint_as_float(f2tf(bgR[i].y * sG));
            pg[2] = __uint_as_float(f2tf(bgR[i].z * sG));
            pg[3] = __uint_as_float(f2tf(bgR[i].w * sG));
            float* pu = Bud + (b_row + i * 8) * BS_LD + b_c4;
            pu[0] = __uint_as_float(f2tf(buR[i].x * sU));
            pu[1] = __uint_as_float(f2tf(buR[i].y * sU));
            pu[2] = __uint_as_float(f2tf(buR[i].z * sU));
            pu[3] = __uint_as_float(f2tf(buR[i].w * sU));
        }
    };

    auto COMPUTE = [&](int st) {
        const float* Ad  = As + st * BM * AS_LD;
        const float* Bgd = Bg + st * BK * BS_LD;
        const float* Bud = Bu + st * BK * BS_LD;
#pragma unroll
        for (int ks = 0; ks < BK; ks += 8) {
            unsigned af[4][4];
#pragma unroll
            for (int mi = 0; mi < 4; mi++) {
                int ar = warp_m * 64 + mi * 16 + g;
                af[mi][0] = __float_as_uint(Ad[ar * AS_LD + ks + tg]);
                af[mi][1] = __float_as_uint(Ad[(ar + 8) * AS_LD + ks + tg]);
                af[mi][2] = __float_as_uint(Ad[ar * AS_LD + ks + tg + 4]);
                af[mi][3] = __float_as_uint(Ad[(ar + 8) * AS_LD + ks + tg + 4]);
            }
            unsigned bgf[4][2], buf_[4][2];
#pragma unroll
            for (int ni = 0; ni < 4; ni++) {
                int bc = warp_n * 32 + ni * 8 + g;
                bgf[ni][0]  = __float_as_uint(Bgd[(ks + tg) * BS_LD + bc]);
                bgf[ni][1]  = __float_as_uint(Bgd[(ks + tg + 4) * BS_LD + bc]);
                buf_[ni][0] = __float_as_uint(Bud[(ks + tg) * BS_LD + bc]);
                buf_[ni][1] = __float_as_uint(Bud[(ks + tg + 4) * BS_LD + bc]);
            }
#pragma unroll
            for (int mi = 0; mi < 4; mi++)
#pragma unroll
                for (int ni = 0; ni < 4; ni++) {
                    mma_tf32(cg[mi][ni], af[mi][0], af[mi][1], af[mi][2], af[mi][3],
                             bgf[ni][0], bgf[ni][1]);
                    mma_tf32(cu[mi][ni], af[mi][0], af[mi][1], af[mi][2], af[mi][3],
                             buf_[ni][0], buf_[ni][1]);
                }
        }
    };

    LOAD(0);
    STORE(0);
    __syncthreads();
    const int KT = H_ / BK;  // 128
    for (int kt = 0; kt < KT; ++kt) {
        int st = kt & 1;
        if (kt + 1 < KT) LOAD((kt + 1) * BK);
        COMPUTE(st);
        if (kt + 1 < KT) STORE(st ^ 1);
        __syncthreads();
    }

    // Epilogue: inter = rw * up * silu(gate)
#pragma unroll
    for (int mi = 0; mi < 4; mi++) {
        int r0 = m0 + warp_m * 64 + mi * 16 + g;
        int r1 = r0 + 8;
        float rw0 = RW[r0 * E_ + e];
        float rw1 = RW[r1 * E_ + e];
#pragma unroll
        for (int ni = 0; ni < 4; ni++) {
            int cn = n0 + warp_n * 32 + ni * 8 + 2 * tg;
            float gv, uv, s;
            gv = cg[mi][ni][0]; uv = cu[mi][ni][0];
            s = 1.0f / (1.0f + expf(-gv));
            g_inter[(size_t)r0 * K2DIM + cn] = rw0 * uv * gv * s;
            gv = cg[mi][ni][1]; uv = cu[mi][ni][1];
            s = 1.0f / (1.0f + expf(-gv));
            g_inter[(size_t)r0 * K2DIM + cn + 1] = rw0 * uv * gv * s;
            gv = cg[mi][ni][2]; uv = cu[mi][ni][2];
            s = 1.0f / (1.0f + expf(-gv));
            g_inter[(size_t)r1 * K2DIM + cn] = rw1 * uv * gv * s;
            gv = cg[mi][ni][3]; uv = cu[mi][ni][3];
            s = 1.0f / (1.0f + expf(-gv));
            g_inter[(size_t)r1 * K2DIM + cn + 1] = rw1 * uv * gv * s;
        }
    }
}

// ---------------------------------------------------------------------------
// Kernel 2: out[t,h] = sum_k inter[t,k] * DN_flat[k,h] * dsc[e, i/128, h/128]
// where DN_flat is down_proj viewed as [E*I, H] row-major (its native layout).
// ---------------------------------------------------------------------------
__global__ void __launch_bounds__(256, 1)
k2_down_combine(const float* __restrict__ DN,   // [E, I, H] = [12288, 2048]
                const float* __restrict__ DNS,  // [E, 6, 16]
                float* __restrict__ OUT)        // [T, H]
{
    extern __shared__ float sm[];
    float* As = sm;             // [2][BM][AS_LD]
    float* Bs = sm + AS_SZ;     // [2][BK][BS_LD]

    const int tid    = threadIdx.x;
    const int wid    = tid >> 5;
    const int lane   = tid & 31;
    const int g      = lane >> 2;
    const int tg     = lane & 3;
    const int warp_m = wid & 1;
    const int warp_n = wid >> 1;

    const int m0 = blockIdx.y * BM;
    const int n0 = blockIdx.x * BN;   // h column

    float cacc[4][4][4];
#pragma unroll
    for (int a = 0; a < 4; a++)
#pragma unroll
        for (int b = 0; b < 4; b++)
#pragma unroll
            for (int c = 0; c < 4; c++) cacc[a][b][c] = 0.f;

    const int a_row = tid >> 2;
    const int a_c4  = (tid & 3) * 4;
    const int b_row = tid >> 5;
    const int b_c4  = (tid & 31) * 4;

    float4 aR[2], bR[2];
    float sB;

    auto LOAD = [&](int k0) {
#pragma unroll
        for (int i = 0; i < 2; i++)
            aR[i] = *reinterpret_cast<const float4*>(
                g_inter + (size_t)(m0 + a_row + i * 64) * K2DIM + k0 + a_c4);
        int e  = k0 / I_;
        int i0 = k0 % I_;
        sB = DNS[(e * 6 + (i0 >> 7)) * 16 + (n0 >> 7)];
#pragma unroll
        for (int i = 0; i < 2; i++)
            bR[i] = *reinterpret_cast<const float4*>(
                DN + (size_t)(k0 + b_row + i * 8) * H_ + n0 + b_c4);
    };

    auto STORE = [&](int st) {
        float* Ad = As + st * BM * AS_LD;
#pragma unroll
        for (int i = 0; i < 2; i++) {
            float* p = Ad + (a_row + i * 64) * AS_LD + a_c4;
            p[0] = __uint_as_float(f2tf(aR[i].x));
            p[1] = __uint_as_float(f2tf(aR[i].y));
            p[2] = __uint_as_float(f2tf(aR[i].z));
            p[3] = __uint_as_float(f2tf(aR[i].w));
        }
        float* Bd = Bs + st * BK * BS_LD;
#pragma unroll
        for (int i = 0; i < 2; i++) {
            float* p = Bd + (b_row + i * 8) * BS_LD + b_c4;
            p[0] = __uint_as_float(f2tf(bR[i].x * sB));
            p[1] = __uint_as_float(f2tf(bR[i].y * sB));
            p[2] = __uint_as_float(f2tf(bR[i].z * sB));
            p[3] = __uint_as_float(f2tf(bR[i].w * sB));
        }
    };

    auto COMPUTE = [&](int st) {
        const float* Ad = As + st * BM * AS_LD;
        const float* Bd = Bs + st * BK * BS_LD;
#pragma unroll
        for (int ks = 0; ks < BK; ks += 8) {
            unsigned af[4][4];
#pragma unroll
            for (int mi = 0; mi < 4; mi++) {
                int ar = warp_m * 64 + mi * 16 + g;
                af[mi][0] = __float_as_uint(Ad[ar * AS_LD + ks + tg]);
                af[mi][1] = __float_as_uint(Ad[(ar + 8) * AS_LD + ks + tg]);
                af[mi][2] = __float_as_uint(Ad[ar * AS_LD + ks + tg + 4]);
                af[mi][3] = __float_as_uint(Ad[(ar + 8) * AS_LD + ks + tg + 4]);
            }
            unsigned bf[4][2];
#pragma unroll
            for (int ni = 0; ni < 4; ni++) {
                int bc = warp_n * 32 + ni * 8 + g;
                bf[ni][0] = __float_as_uint(Bd[(ks + tg) * BS_LD + bc]);
                bf[ni][1] = __float_as_uint(Bd[(ks + tg + 4) * BS_LD + bc]);
            }
#pragma unroll
            for (int mi = 0; mi < 4; mi++)
#pragma unroll
                for (int ni = 0; ni < 4; ni++)
                    mma_tf32(cacc[mi][ni], af[mi][0], af[mi][1], af[mi][2], af[mi][3],
                             bf[ni][0], bf[ni][1]);
        }
    };

    LOAD(0);
    STORE(0);
    __syncthreads();
    const int KT = K2DIM / BK;  // 768
    for (int kt = 0; kt < KT; ++kt) {
        int st = kt & 1;
        if (kt + 1 < KT) LOAD((kt + 1) * BK);
        COMPUTE(st);
        if (kt + 1 < KT) STORE(st ^ 1);
        __syncthreads();
    }

#pragma unroll
    for (int mi = 0; mi < 4; mi++) {
        int r0 = m0 + warp_m * 64 + mi * 16 + g;
        int r1 = r0 + 8;
#pragma unroll
        for (int ni = 0; ni < 4; ni++) {
            int cn = n0 + warp_n * 32 + ni * 8 + 2 * tg;
            OUT[(size_t)r0 * H_ + cn]     = cacc[mi][ni][0];
            OUT[(size_t)r0 * H_ + cn + 1] = cacc[mi][ni][1];
            OUT[(size_t)r1 * H_ + cn]     = cacc[mi][ni][2];
            OUT[(size_t)r1 * H_ + cn + 1] = cacc[mi][ni][3];
        }
    }
}

// ---------------------------------------------------------------------------
extern "C" void kernel_launch(void* const* d_in, const int* in_sizes, int n_in,
                              void* d_out, int out_size) {
    (void)in_sizes; (void)n_in; (void)out_size;
    const float* X   = (const float*)d_in[0];  // hidden_states [B,S,H]
    const float* RW  = (const float*)d_in[1];  // routing_weights [T,E]
    const float* GU  = (const float*)d_in[2];  // gate_up_proj [E,H,2I]
    const float* GUS = (const float*)d_in[3];  // gate_up_proj_scale_inv [E,16,12]
    const float* DN  = (const float*)d_in[4];  // down_proj [E,I,H]
    const float* DNS = (const float*)d_in[5];  // down_proj_scale_inv [E,6,16]
    // d_in[6] = router_indices: unused by the reference computation
    float* OUT = (float*)d_out;

    cudaFuncSetAttribute(k1_gateup_silu,
                         cudaFuncAttributeMaxDynamicSharedMemorySize, SMEM1_BYTES);
    cudaFuncSetAttribute(k2_down_combine,
                         cudaFuncAttributeMaxDynamicSharedMemorySize, SMEM2_BYTES);

    dim3 grid1(K2DIM / BN, T_ / BM);  // (96, 32)
    k1_gateup_silu<<<grid1, 256, SMEM1_BYTES>>>(X, RW, GU, GUS);

    dim3 grid2(H_ / BN, T_ / BM);    // (16, 32)
    k2_down_combine<<<grid2, 256, SMEM2_BYTES>>>(DN, DNS, OUT);
}

// round 2
// speedup vs baseline: 1.0017x; 1.0017x over previous
#include <cuda_runtime.h>
#include <cuda_bf16.h>
#include <math.h>
#include <stdint.h>

// Problem constants
#define E_   16
#define H_   2048
#define I_   768
#define T_   4096
#define TWOI 1536
#define K2DIM (E_ * I_)   // 12288

// Tiling
#define BM 128
#define BN 128
#define BK 16
#define AS_LD 20     // 16 + 4 pad  -> bank (20r+c)%32 conflict-free for frag reads
#define BS_LD 132    // 128 + 4 pad -> bank (4k+n)%32 conflict-free for frag reads

#define AS_SZ (2 * BM * AS_LD)           // floats, double buffered
#define BT_SZ (2 * BK * BS_LD)           // floats, double buffered (one B tile)
#define SMEM1_FLOATS (AS_SZ + 2 * BT_SZ) // A + Bgate + Bup
#define SMEM1_BYTES  (SMEM1_FLOATS * 4)  // 54,272 B
#define SMEM2_FLOATS (AS_SZ + BT_SZ)
#define SMEM2_BYTES  (SMEM2_FLOATS * 4)  // 37,376 B

// 201 MB scratch for inter = rw * up * silu(gate), laid out [T, E*I]
__device__ float g_inter[(size_t)T_ * K2DIM];

__device__ __forceinline__ unsigned f2tf(float x) {
    unsigned u;
    asm("cvt.rna.tf32.f32 %0, %1;" : "=r"(u) : "f"(x));
    return u;
}

__device__ __forceinline__ void mma_tf32(float c[4],
                                         unsigned a0, unsigned a1, unsigned a2, unsigned a3,
                                         unsigned b0, unsigned b1) {
    asm volatile(
        "mma.sync.aligned.m16n8k8.row.col.f32.tf32.tf32.f32 "
        "{%0,%1,%2,%3}, {%4,%5,%6,%7}, {%8,%9}, {%0,%1,%2,%3};\n"
        : "+f"(c[0]), "+f"(c[1]), "+f"(c[2]), "+f"(c[3])
        : "r"(a0), "r"(a1), "r"(a2), "r"(a3), "r"(b0), "r"(b1));
}

// ---------------------------------------------------------------------------
// Kernel 1: inter[t, e*768+j] = rw[t,e] * up * silu(gate)
//   gate = sum_h X[t,h] * GU[e,h,j]      * gsc[e,h/128, j/128]
//   up   = sum_h X[t,h] * GU[e,h,768+j]  * gsc[e,h/128, 6 + j/128]
// Block: 128 rows (t) x 128 cols (j local within expert). 768 % 128 == 0, so
// each block sits inside one expert and one scale column.
// ---------------------------------------------------------------------------
__global__ void __launch_bounds__(256, 1)
k1_gateup_silu(const float* __restrict__ X,    // [T, H]
               const float* __restrict__ RW,   // [T, E]
               const float* __restrict__ GU,   // [E, H, 2I]
               const float* __restrict__ GUS)  // [E, 16, 12]
{
    extern __shared__ float sm[];
    float* As = sm;                 // [2][BM][AS_LD]
    float* Bg = sm + AS_SZ;         // [2][BK][BS_LD]
    float* Bu = Bg + BT_SZ;         // [2][BK][BS_LD]

    const int tid    = threadIdx.x;
    const int wid    = tid >> 5;
    const int lane   = tid & 31;
    const int g      = lane >> 2;   // 0..7
    const int tg     = lane & 3;    // 0..3
    const int warp_m = wid & 1;     // 0..1 -> 64 rows each
    const int warp_n = wid >> 1;    // 0..3 -> 32 cols each

    const int m0 = blockIdx.y * BM;
    const int n0 = blockIdx.x * BN;     // global inter column
    const int e  = n0 / I_;
    const int j0 = n0 % I_;             // multiple of 128

    const float* guE = GU + (size_t)e * H_ * TWOI;
    const float* gsE = GUS + e * 16 * 12;

    float cg[4][4][4], cu[4][4][4];
#pragma unroll
    for (int a = 0; a < 4; a++)
#pragma unroll
        for (int b = 0; b < 4; b++)
#pragma unroll
            for (int c = 0; c < 4; c++) { cg[a][b][c] = 0.f; cu[a][b][c] = 0.f; }

    // gmem -> reg staging layout
    const int a_row = tid >> 2;            // 0..63 (two iters: +0, +64)
    const int a_c4  = (tid & 3) * 4;       // 0,4,8,12
    const int b_row = tid >> 5;            // 0..7 (two iters: +0, +8)
    const int b_c4  = (tid & 31) * 4;      // 0..124

    float4 aR[2], bgR[2], buR[2];
    float sG, sU;

    auto LOAD = [&](int k0) {
#pragma unroll
        for (int i = 0; i < 2; i++)
            aR[i] = *reinterpret_cast<const float4*>(
                X + (size_t)(m0 + a_row + i * 64) * H_ + k0 + a_c4);
        sG = gsE[(k0 >> 7) * 12 + (j0 >> 7)];
        sU = gsE[(k0 >> 7) * 12 + 6 + (j0 >> 7)];
#pragma unroll
        for (int i = 0; i < 2; i++) {
            size_t roff = (size_t)(k0 + b_row + i * 8) * TWOI;
            bgR[i] = *reinterpret_cast<const float4*>(guE + roff + j0 + b_c4);
            buR[i] = *reinterpret_cast<const float4*>(guE + roff + I_ + j0 + b_c4);
        }
    };

    auto STORE = [&](int st) {
        float* Ad = As + st * BM * AS_LD;
#pragma unroll
        for (int i = 0; i < 2; i++) {
            float* p = Ad + (a_row + i * 64) * AS_LD + a_c4;
            p[0] = __uint_as_float(f2tf(aR[i].x));
            p[1] = __uint_as_float(f2tf(aR[i].y));
            p[2] = __uint_as_float(f2tf(aR[i].z));
            p[3] = __uint_as_float(f2tf(aR[i].w));
        }
        float* Bgd = Bg + st * BK * BS_LD;
        float* Bud = Bu + st * BK * BS_LD;
#pragma unroll
        for (int i = 0; i < 2; i++) {
            float* pg = Bgd + (b_row + i * 8) * BS_LD + b_c4;
            pg[0] = __uint_as_float(f2tf(bgR[i].x * sG));
            pg[1] = __uint_as_float(f2tf(bgR[i].y * sG));
            pg[2] = __uint_as_float(f2tf(bgR[i].z * sG));
            pg[3] = __uint_as_float(f2tf(bgR[i].w * sG));
            float* pu = Bud + (b_row + i * 8) * BS_LD + b_c4;
            pu[0] = __uint_as_float(f2tf(buR[i].x * sU));
            pu[1] = __uint_as_float(f2tf(buR[i].y * sU));
            pu[2] = __uint_as_float(f2tf(buR[i].z * sU));
            pu[3] = __uint_as_float(f2tf(buR[i].w * sU));
        }
    };

    auto COMPUTE = [&](int st) {
        const float* Ad  = As + st * BM * AS_LD;
        const float* Bgd = Bg + st * BK * BS_LD;
        const float* Bud = Bu + st * BK * BS_LD;
#pragma unroll
        for (int ks = 0; ks < BK; ks += 8) {
            unsigned af[4][4];
#pragma unroll
            for (int mi = 0; mi < 4; mi++) {
                int ar = warp_m * 64 + mi * 16 + g;
                af[mi][0] = __float_as_uint(Ad[ar * AS_LD + ks + tg]);
                af[mi][1] = __float_as_uint(Ad[(ar + 8) * AS_LD + ks + tg]);
                af[mi][2] = __float_as_uint(Ad[ar * AS_LD + ks + tg + 4]);
                af[mi][3] = __float_as_uint(Ad[(ar + 8) * AS_LD + ks + tg + 4]);
            }
            unsigned bgf[4][2], buf_[4][2];
#pragma unroll
            for (int ni = 0; ni < 4; ni++) {
                int bc = warp_n * 32 + ni * 8 + g;
                bgf[ni][0]  = __float_as_uint(Bgd[(ks + tg) * BS_LD + bc]);
                bgf[ni][1]  = __float_as_uint(Bgd[(ks + tg + 4) * BS_LD + bc]);
                buf_[ni][0] = __float_as_uint(Bud[(ks + tg) * BS_LD + bc]);
                buf_[ni][1] = __float_as_uint(Bud[(ks + tg + 4) * BS_LD + bc]);
            }
#pragma unroll
            for (int mi = 0; mi < 4; mi++)
#pragma unroll
                for (int ni = 0; ni < 4; ni++) {
                    mma_tf32(cg[mi][ni], af[mi][0], af[mi][1], af[mi][2], af[mi][3],
                             bgf[ni][0], bgf[ni][1]);
                    mma_tf32(cu[mi][ni], af[mi][0], af[mi][1], af[mi][2], af[mi][3],
                             buf_[ni][0], buf_[ni][1]);
                }
        }
    };

    LOAD(0);
    STORE(0);
    __syncthreads();
    const int KT = H_ / BK;  // 128
    for (int kt = 0; kt < KT; ++kt) {
        int st = kt & 1;
        if (kt + 1 < KT) LOAD((kt + 1) * BK);
        COMPUTE(st);
        if (kt + 1 < KT) STORE(st ^ 1);
        __syncthreads();
    }

    // Epilogue: inter = rw * up * silu(gate)
#pragma unroll
    for (int mi = 0; mi < 4; mi++) {
        int r0 = m0 + warp_m * 64 + mi * 16 + g;
        int r1 = r0 + 8;
        float rw0 = RW[r0 * E_ + e];
        float rw1 = RW[r1 * E_ + e];
#pragma unroll
        for (int ni = 0; ni < 4; ni++) {
            int cn = n0 + warp_n * 32 + ni * 8 + 2 * tg;
            float gv, uv, s;
            gv = cg[mi][ni][0]; uv = cu[mi][ni][0];
            s = 1.0f / (1.0f + expf(-gv));
            g_inter[(size_t)r0 * K2DIM + cn] = rw0 * uv * gv * s;
            gv = cg[mi][ni][1]; uv = cu[mi][ni][1];
            s = 1.0f / (1.0f + expf(-gv));
            g_inter[(size_t)r0 * K2DIM + cn + 1] = rw0 * uv * gv * s;
            gv = cg[mi][ni][2]; uv = cu[mi][ni][2];
            s = 1.0f / (1.0f + expf(-gv));
            g_inter[(size_t)r1 * K2DIM + cn] = rw1 * uv * gv * s;
            gv = cg[mi][ni][3]; uv = cu[mi][ni][3];
            s = 1.0f / (1.0f + expf(-gv));
            g_inter[(size_t)r1 * K2DIM + cn + 1] = rw1 * uv * gv * s;
        }
    }
}

// ---------------------------------------------------------------------------
// Kernel 2: out[t,h] = sum_k inter[t,k] * DN_flat[k,h] * dsc[e, i/128, h/128]
// where DN_flat is down_proj viewed as [E*I, H] row-major (its native layout).
// ---------------------------------------------------------------------------
__global__ void __launch_bounds__(256, 1)
k2_down_combine(const float* __restrict__ DN,   // [E, I, H] = [12288, 2048]
                const float* __restrict__ DNS,  // [E, 6, 16]
                float* __restrict__ OUT)        // [T, H]
{
    extern __shared__ float sm[];
    float* As = sm;             // [2][BM][AS_LD]
    float* Bs = sm + AS_SZ;     // [2][BK][BS_LD]

    const int tid    = threadIdx.x;
    const int wid    = tid >> 5;
    const int lane   = tid & 31;
    const int g      = lane >> 2;
    const int tg     = lane & 3;
    const int warp_m = wid & 1;
    const int warp_n = wid >> 1;

    const int m0 = blockIdx.y * BM;
    const int n0 = blockIdx.x * BN;   // h column

    float cacc[4][4][4];
#pragma unroll
    for (int a = 0; a < 4; a++)
#pragma unroll
        for (int b = 0; b < 4; b++)
#pragma unroll
            for (int c = 0; c < 4; c++) cacc[a][b][c] = 0.f;

    const int a_row = tid >> 2;
    const int a_c4  = (tid & 3) * 4;
    const int b_row = tid >> 5;
    const int b_c4  = (tid & 31) * 4;

    float4 aR[2], bR[2];
    float sB;

    auto LOAD = [&](int k0) {
#pragma unroll
        for (int i = 0; i < 2; i++)
            aR[i] = *reinterpret_cast<const float4*>(
                g_inter + (size_t)(m0 + a_row + i * 64) * K2DIM + k0 + a_c4);
        int e  = k0 / I_;
        int i0 = k0 % I_;
        sB = DNS[(e * 6 + (i0 >> 7)) * 16 + (n0 >> 7)];
#pragma unroll
        for (int i = 0; i < 2; i++)
            bR[i] = *reinterpret_cast<const float4*>(
                DN + (size_t)(k0 + b_row + i * 8) * H_ + n0 + b_c4);
    };

    auto STORE = [&](int st) {
        float* Ad = As + st * BM * AS_LD;
#pragma unroll
        for (int i = 0; i < 2; i++) {
            float* p = Ad + (a_row + i * 64) * AS_LD + a_c4;
            p[0] = __uint_as_float(f2tf(aR[i].x));
            p[1] = __uint_as_float(f2tf(aR[i].y));
            p[2] = __uint_as_float(f2tf(aR[i].z));
            p[3] = __uint_as_float(f2tf(aR[i].w));
        }
        float* Bd = Bs + st * BK * BS_LD;
#pragma unroll
        for (int i = 0; i < 2; i++) {
            float* p = Bd + (b_row + i * 8) * BS_LD + b_c4;
            p[0] = __uint_as_float(f2tf(bR[i].x * sB));
            p[1] = __uint_as_float(f2tf(bR[i].y * sB));
            p[2] = __uint_as_float(f2tf(bR[i].z * sB));
            p[3] = __uint_as_float(f2tf(bR[i].w * sB));
        }
    };

    auto COMPUTE = [&](int st) {
        const float* Ad = As + st * BM * AS_LD;
        const float* Bd = Bs + st * BK * BS_LD;
#pragma unroll
        for (int ks = 0; ks < BK; ks += 8) {
            unsigned af[4][4];
#pragma unroll
            for (int mi = 0; mi < 4; mi++) {
                int ar = warp_m * 64 + mi * 16 + g;
                af[mi][0] = __float_as_uint(Ad[ar * AS_LD + ks + tg]);
                af[mi][1] = __float_as_uint(Ad[(ar + 8) * AS_LD + ks + tg]);
                af[mi][2] = __float_as_uint(Ad[ar * AS_LD + ks + tg + 4]);
                af[mi][3] = __float_as_uint(Ad[(ar + 8) * AS_LD + ks + tg + 4]);
            }
            unsigned bf[4][2];
#pragma unroll
            for (int ni = 0; ni < 4; ni++) {
                int bc = warp_n * 32 + ni * 8 + g;
                bf[ni][0] = __float_as_uint(Bd[(ks + tg) * BS_LD + bc]);
                bf[ni][1] = __float_as_uint(Bd[(ks + tg + 4) * BS_LD + bc]);
            }
#pragma unroll
            for (int mi = 0; mi < 4; mi++)
#pragma unroll
                for (int ni = 0; ni < 4; ni++)
                    mma_tf32(cacc[mi][ni], af[mi][0], af[mi][1], af[mi][2], af[mi][3],
                             bf[ni][0], bf[ni][1]);
        }
    };

    LOAD(0);
    STORE(0);
    __syncthreads();
    const int KT = K2DIM / BK;  // 768
    for (int kt = 0; kt < KT; ++kt) {
        int st = kt & 1;
        if (kt + 1 < KT) LOAD((kt + 1) * BK);
        COMPUTE(st);
        if (kt + 1 < KT) STORE(st ^ 1);
        __syncthreads();
    }

#pragma unroll
    for (int mi = 0; mi < 4; mi++) {
        int r0 = m0 + warp_m * 64 + mi * 16 + g;
        int r1 = r0 + 8;
#pragma unroll
        for (int ni = 0; ni < 4; ni++) {
            int cn = n0 + warp_n * 32 + ni * 8 + 2 * tg;
            OUT[(size_t)r0 * H_ + cn]     = cacc[mi][ni][0];
            OUT[(size_t)r0 * H_ + cn + 1] = cacc[mi][ni][1];
            OUT[(size_t)r1 * H_ + cn]     = cacc[mi][ni][2];
            OUT[(size_t)r1 * H_ + cn + 1] = cacc[mi][ni][3];
        }
    }
}

// ---------------------------------------------------------------------------
extern "C" void kernel_launch(void* const* d_in, const int* in_sizes, int n_in,
                              void* d_out, int out_size) {
    (void)in_sizes; (void)n_in; (void)out_size;
    const float* X   = (const float*)d_in[0];  // hidden_states [B,S,H]
    const float* RW  = (const float*)d_in[1];  // routing_weights [T,E]
    const float* GU  = (const float*)d_in[2];  // gate_up_proj [E,H,2I]
    const float* GUS = (const float*)d_in[3];  // gate_up_proj_scale_inv [E,16,12]
    const float* DN  = (const float*)d_in[4];  // down_proj [E,I,H]
    const float* DNS = (const float*)d_in[5];  // down_proj_scale_inv [E,6,16]
    // d_in[6] = router_indices: unused by the reference computation
    float* OUT = (float*)d_out;

    cudaFuncSetAttribute(k1_gateup_silu,
                         cudaFuncAttributeMaxDynamicSharedMemorySize, SMEM1_BYTES);
    cudaFuncSetAttribute(k2_down_combine,
                         cudaFuncAttributeMaxDynamicSharedMemorySize, SMEM2_BYTES);

    dim3 grid1(K2DIM / BN, T_ / BM);  // (96, 32)
    k1_gateup_silu<<<grid1, 256, SMEM1_BYTES>>>(X, RW, GU, GUS);

    dim3 grid2(H_ / BN, T_ / BM);    // (16, 32)
    k2_down_combine<<<grid2, 256, SMEM2_BYTES>>>(DN, DNS, OUT);
}

// round 4
// speedup vs baseline: 1.0315x; 1.0297x over previous
#include <cuda_runtime.h>
#include <stdint.h>
#include <math.h>

#define E_ 16
#define H_ 2048
#define I_ 768
#define TWOI 1536
#define T_ 4096
#define K2DIM 12288

#define A_STRIDE 80
#define B_STRIDE 80
#define A_STAGE (128 * A_STRIDE)             // 10240 B
#define B_STAGE (256 * B_STRIDE)             // 20480 B
#define SMEM_BYTES (2 * A_STAGE + 2 * B_STAGE)  // 61440 B

__device__ float g_inter[(size_t)T_ * K2DIM];

static __device__ __forceinline__ uint32_t f2tf(float x) {
    uint32_t u; asm("cvt.rna.tf32.f32 %0, %1;" : "=r"(u) : "f"(x)); return u;
}
static __device__ __forceinline__ void ldsm4(uint32_t r[4], uint32_t a) {
    asm volatile("ldmatrix.sync.aligned.m8n8.x4.shared.b16 {%0,%1,%2,%3}, [%4];"
                 : "=r"(r[0]), "=r"(r[1]), "=r"(r[2]), "=r"(r[3]) : "r"(a));
}
static __device__ __forceinline__ void sts128(uint32_t a, uint32_t x, uint32_t y, uint32_t z, uint32_t w) {
    asm volatile("st.shared.v4.b32 [%0], {%1,%2,%3,%4};" :: "r"(a), "r"(x), "r"(y), "r"(z), "r"(w) : "memory");
}
static __device__ __forceinline__ void cp16(uint32_t d, const void* s) {
    asm volatile("cp.async.ca.shared.global [%0], [%1], 16;" :: "r"(d), "l"(s) : "memory");
}
static __device__ __forceinline__ void mma_tf32(float c[4], const uint32_t a[4], uint32_t b0, uint32_t b1) {
    asm volatile("mma.sync.aligned.m16n8k8.row.col.f32.tf32.tf32.f32 "
                 "{%0,%1,%2,%3}, {%4,%5,%6,%7}, {%8,%9}, {%0,%1,%2,%3};"
                 : "+f"(c[0]), "+f"(c[1]), "+f"(c[2]), "+f"(c[3])
                 : "r"(a[0]), "r"(a[1]), "r"(a[2]), "r"(a[3]), "r"(b0), "r"(b1));
}

// MODE 1: inter[t, e*768+j] = rw * up * silu(gate); A=X[T,H], B=GU[e], K=2048.
//         CTA covers 128 t-rows x (gate 128 | up 128) of one expert j-block,
//         interleaved in 32-col groups so each warp holds gate&up of same cols.
// MODE 2: out = inter @ DN_flat; A=g_inter[T,12288], B=DN[12288,2048], K=12288.
template<int MODE>
__global__ void __launch_bounds__(256, 1)
moe_mma(const float* __restrict__ Ain, const float* __restrict__ Bin,
        const float* __restrict__ SC, const float* __restrict__ RW,
        float* __restrict__ OUT)
{
    extern __shared__ char smraw[];
    const uint32_t sb = (uint32_t)__cvta_generic_to_shared(smraw);
    const uint32_t sA = sb, sB = sb + 2 * A_STAGE;

    const int tid = threadIdx.x, lane = tid & 31, wid = tid >> 5;
    const int warp_m = wid & 1, warp_n = wid >> 1;
    const int m0 = blockIdx.x * 128;

    int e = 0, j0 = 0, n0 = 0, lda, ldb, NC;
    const float* Ap;
    if (MODE == 1) { e = blockIdx.y / 6; j0 = (blockIdx.y % 6) * 128; Ap = Ain; lda = H_; ldb = TWOI; NC = H_ / 16; }
    else           { n0 = blockIdx.y * 256; Ap = g_inter; lda = K2DIM; ldb = H_; NC = K2DIM / 16; }

    // ---- producer B thread map: 256 thr = 2 groups x (32 n-quads x 4 k-quads)
    const int grp = tid >> 7, tl = tid & 127, jb = tl >> 2, kb = tl & 3;
    int destbase;
    const float* bsrc;
    if (MODE == 1) {
        destbase = ((jb >> 3) << 6) + (grp ? 32 : 0) + ((jb & 7) << 2);
        bsrc = Bin + (size_t)e * H_ * TWOI + (grp ? I_ : 0) + j0 + jb * 4;
    } else {
        destbase = grp * 128 + (jb << 2);
        bsrc = Bin + n0 + grp * 128 + jb * 4;
    }
    // ---- producer A (cp.async): thread -> one row, two 16B k-chunks
    const int arow = tid & 127, ag = tid >> 7;

    // ---- ldmatrix per-lane constants
    const int mat = lane >> 3, q = lane & 7;
    const int rA = ((mat & 1) << 3) + q, cA = (mat >> 1) << 4;
    const int rB = ((mat >> 1) << 3) + q, cB = (mat & 1) << 4;

    float acc[4][8][4];
#pragma unroll
    for (int a = 0; a < 4; a++)
#pragma unroll
        for (int b = 0; b < 8; b++)
#pragma unroll
            for (int c = 0; c < 4; c++) acc[a][b][c] = 0.f;

    float4 bst[4];
    float scl;

    auto LDGB = [&](int c) {
        const int k0 = c * 16;
#pragma unroll
        for (int kk = 0; kk < 4; kk++)
            bst[kk] = *reinterpret_cast<const float4*>(bsrc + (size_t)(k0 + kb * 4 + kk) * ldb);
        if (MODE == 1) {
            scl = SC[e * 192 + (k0 >> 7) * 12 + (grp ? 6 : 0) + (j0 >> 7)];
        } else {
            int ee = k0 / I_, band = (k0 - ee * I_) >> 7;
            scl = SC[(ee * 6 + band) * 16 + (n0 >> 7) + grp];
        }
    };
    auto CPA = [&](int c, int buf) {
        const int k0 = c * 16;
        const uint32_t d = sA + buf * A_STAGE + arow * A_STRIDE;
        const float* s = Ap + (size_t)(m0 + arow) * lda + k0;
        cp16(d + ag * 16, s + ag * 4);
        cp16(d + (ag + 2) * 16, s + (ag + 2) * 4);
        asm volatile("cp.async.commit_group;" ::: "memory");
    };
    auto STSB = [&](int buf) {
        const uint32_t bb = sB + buf * B_STAGE;
        const float* p = (const float*)bst;
#pragma unroll
        for (int jj = 0; jj < 4; jj++) {
            sts128(bb + (uint32_t)(destbase + jj) * B_STRIDE + kb * 16,
                   f2tf(p[0 * 4 + jj] * scl), f2tf(p[1 * 4 + jj] * scl),
                   f2tf(p[2 * 4 + jj] * scl), f2tf(p[3 * 4 + jj] * scl));
        }
    };
    auto COMPUTE = [&](int buf) {
        const uint32_t ab = sA + buf * A_STAGE, bb = sB + buf * B_STAGE;
#pragma unroll
        for (int s = 0; s < 2; s++) {
            uint32_t af[4][4];
#pragma unroll
            for (int mi = 0; mi < 4; mi++) {
                ldsm4(af[mi], ab + (uint32_t)(warp_m * 64 + mi * 16 + rA) * A_STRIDE + s * 32 + cA);
#pragma unroll
                for (int i = 0; i < 4; i++) af[mi][i] = f2tf(__uint_as_float(af[mi][i]));
            }
            uint32_t bf[4][4];
#pragma unroll
            for (int np = 0; np < 4; np++)
                ldsm4(bf[np], bb + (uint32_t)(warp_n * 64 + np * 16 + rB) * B_STRIDE + s * 32 + cB);
#pragma unroll
            for (int mi = 0; mi < 4; mi++)
#pragma unroll
                for (int nt = 0; nt < 8; nt++)
                    mma_tf32(acc[mi][nt], af[mi], bf[nt >> 1][(nt & 1) * 2], bf[nt >> 1][(nt & 1) * 2 + 1]);
        }
    };

    // prologue
    LDGB(0); CPA(0, 0); STSB(0);
    asm volatile("cp.async.wait_group 0;" ::: "memory");
    __syncthreads();

#pragma unroll 1
    for (int c = 0; c < NC; c++) {
        const int buf = c & 1;
        const bool more = (c + 1 < NC);
        if (more) { LDGB(c + 1); CPA(c + 1, buf ^ 1); }
        COMPUTE(buf);
        if (more) STSB(buf ^ 1);
        asm volatile("cp.async.wait_group 0;" ::: "memory");
        __syncthreads();
    }

    // ---- epilogue
    const int g = lane >> 2, tg = lane & 3;
    if (MODE == 1) {
#pragma unroll
        for (int mi = 0; mi < 4; mi++) {
            const int r0 = m0 + warp_m * 64 + mi * 16 + g, r1 = r0 + 8;
            const float rw0 = RW[r0 * E_ + e], rw1 = RW[r1 * E_ + e];
#pragma unroll
            for (int nt = 0; nt < 4; nt++) {
                const size_t col = (size_t)e * I_ + j0 + warp_n * 32 + nt * 8 + tg * 2;
                float gv, uv; float2 v;
                gv = acc[mi][nt][0]; uv = acc[mi][nt + 4][0]; v.x = rw0 * uv * gv / (1.f + __expf(-gv));
                gv = acc[mi][nt][1]; uv = acc[mi][nt + 4][1]; v.y = rw0 * uv * gv / (1.f + __expf(-gv));
                *reinterpret_cast<float2*>(g_inter + (size_t)r0 * K2DIM + col) = v;
                gv = acc[mi][nt][2]; uv = acc[mi][nt + 4][2]; v.x = rw1 * uv * gv / (1.f + __expf(-gv));
                gv = acc[mi][nt][3]; uv = acc[mi][nt + 4][3]; v.y = rw1 * uv * gv / (1.f + __expf(-gv));
                *reinterpret_cast<float2*>(g_inter + (size_t)r1 * K2DIM + col) = v;
            }
        }
    } else {
#pragma unroll
        for (int mi = 0; mi < 4; mi++) {
            const int r0 = m0 + warp_m * 64 + mi * 16 + g, r1 = r0 + 8;
#pragma unroll
            for (int nt = 0; nt < 8; nt++) {
                const size_t col = (size_t)n0 + warp_n * 64 + nt * 8 + tg * 2;
                float2 v;
                v.x = acc[mi][nt][0]; v.y = acc[mi][nt][1];
                *reinterpret_cast<float2*>(OUT + (size_t)r0 * H_ + col) = v;
                v.x = acc[mi][nt][2]; v.y = acc[mi][nt][3];
                *reinterpret_cast<float2*>(OUT + (size_t)r1 * H_ + col) = v;
            }
        }
    }
}

extern "C" void kernel_launch(void* const* d_in, const int* in_sizes, int n_in,
                              void* d_out, int out_size) {
    (void)in_sizes; (void)n_in; (void)out_size;
    const float* X   = (const float*)d_in[0];  // hidden_states [T,H]
    const float* RW  = (const float*)d_in[1];  // routing_weights [T,E]
    const float* GU  = (const float*)d_in[2];  // gate_up_proj [E,H,2I]
    const float* GUS = (const float*)d_in[3];  // [E,16,12]
    const float* DN  = (const float*)d_in[4];  // down_proj [E,I,H]
    const float* DNS = (const float*)d_in[5];  // [E,6,16]
    float* OUT = (float*)d_out;

    cudaFuncSetAttribute(moe_mma<1>, cudaFuncAttributeMaxDynamicSharedMemorySize, SMEM_BYTES);
    cudaFuncSetAttribute(moe_mma<2>, cudaFuncAttributeMaxDynamicSharedMemorySize, SMEM_BYTES);

    // grid.x = m-tiles (fast) -> weights stream once per wave, activations L2-resident
    moe_mma<1><<<dim3(32, 96), 256, SMEM_BYTES>>>(X, GU, GUS, RW, nullptr);
    moe_mma<2><<<dim3(32, 8), 256, SMEM_BYTES>>>(nullptr, DN, DNS, nullptr, OUT);
}